// round 1
// baseline (speedup 1.0000x reference)
#include <cuda_runtime.h>
#include <math.h>

#define Bb 64
#define Tt 2048
#define Vv 256
#define Uu 256
#define Ss 513            // 2U+1
#define NEGV (-1e30f)
#define DEPTH 8           // row ring slots (power of 2)
#define PD 7              // prefetch distance (DEPTH-1)

__device__ float g_lse[Bb * Tt];
__device__ float g_nll[Bb];

// ---------------------------------------------------------------------------
// Kernel 1: lse[b,t] = logsumexp(logits[b,t,:]) over V=256. One warp per row.
// ---------------------------------------------------------------------------
__global__ void __launch_bounds__(256) lse_kernel(const float* __restrict__ logits) {
    int gw = (blockIdx.x * 256 + threadIdx.x) >> 5;   // global warp = row id
    int lane = threadIdx.x & 31;
    if (gw >= Bb * Tt) return;
    const float4* p = reinterpret_cast<const float4*>(logits + (size_t)gw * Vv);
    float4 a = p[lane];
    float4 c = p[lane + 32];
    float m = fmaxf(fmaxf(fmaxf(a.x, a.y), fmaxf(a.z, a.w)),
                    fmaxf(fmaxf(c.x, c.y), fmaxf(c.z, c.w)));
#pragma unroll
    for (int o = 16; o; o >>= 1) m = fmaxf(m, __shfl_xor_sync(0xffffffffu, m, o));
    float s = expf(a.x - m) + expf(a.y - m) + expf(a.z - m) + expf(a.w - m)
            + expf(c.x - m) + expf(c.y - m) + expf(c.z - m) + expf(c.w - m);
#pragma unroll
    for (int o = 16; o; o >>= 1) s += __shfl_xor_sync(0xffffffffu, s, o);
    if (lane == 0) g_lse[gw] = m + logf(s);
}

// ---------------------------------------------------------------------------
// Kernel 2: Viterbi forward over the CTC extended graph. One block per batch.
// alpha_t[s] = max(alpha[s], alpha[s-1], skip? alpha[s-2]) + (row[ext_s]-lse_t)
// Result needed: max(alpha_{L-1}[2Ut], alpha_{L-1}[2Ut-1])  (== masked nll sum)
// ---------------------------------------------------------------------------
__global__ void __launch_bounds__(256) dp_kernel(const float* __restrict__ logits,
                                                 const int*  __restrict__ targets,
                                                 const int*  __restrict__ loglen,
                                                 const int*  __restrict__ tgtlen) {
    __shared__ float sAlpha[2][Ss + 3];   // +2 index shift: [0],[1] stay NEG forever
    __shared__ float sRow[DEPTH][Vv];     // logits row ring
    __shared__ float sLse[Tt];

    const int b   = blockIdx.x;
    const int tid = threadIdx.x;
    const int L   = loglen[b];
    const int Ut  = tgtlen[b];
    const int Sb  = 2 * Ut + 1;
    const float* lg = logits + (size_t)b * Tt * Vv;

    // preload lse for this batch
    for (int i = tid; i < Tt; i += 256) sLse[i] = g_lse[b * Tt + i];
    // init alpha buffers to NEG
    for (int i = tid; i < Ss + 3; i += 256) { sAlpha[0][i] = NEGV; sAlpha[1][i] = NEGV; }

    // per-state metadata (thread owns states tid and tid+256; tid 0 also state 512)
    int ext0, ext1, v0, v1; bool sk0, sk1;
    {
        int s = tid;
        bool odd = (s & 1);
        int lp = s >> 1;
        ext0 = odd ? targets[b * Uu + lp] : 0;
        int em2 = (s >= 2) ? (odd ? targets[b * Uu + lp - 1] : 0) : 0;
        sk0 = (s >= 2) && odd && (ext0 != em2);
        v0 = (s < Sb);
    }
    {
        int s = tid + 256;
        bool odd = (s & 1);
        int lp = s >> 1;
        ext1 = odd ? targets[b * Uu + lp] : 0;
        int em2 = odd ? targets[b * Uu + lp - 1] : 0;   // s>=258 so lp-1 >= 127 safe
        sk1 = odd && (ext1 != em2);                      // s>=2 always
        v1 = (s < Sb);
    }
    const int v512 = (512 < Sb);

    // prologue: prefetch rows 0..PD-1 (threads 0..63 copy 16B each)
    for (int d = 0; d < PD; ++d) {
        if (tid < 64) {
            unsigned saddr = (unsigned)__cvta_generic_to_shared(&sRow[d][tid * 4]);
            const float* gaddr = lg + (size_t)d * Vv + tid * 4;
            asm volatile("cp.async.cg.shared.global [%0], [%1], 16;\n"
                         :: "r"(saddr), "l"(gaddr));
        }
        asm volatile("cp.async.commit_group;\n");
    }

    __syncthreads();
    if (tid == 0) sAlpha[0][2] = 0.0f;   // seed: makes alpha_0[s<=1] = em_0 exactly

    int pb = 0;
    for (int t = 0; t < L; ++t) {
        asm volatile("cp.async.wait_group %0;\n" :: "n"(PD - 1)); // row t landed
        __syncthreads();  // row t visible, alpha(t-1) visible, slot(t-1) free

        // prefetch row t+PD into slot of row t-1
        int tp = t + PD;
        if (tid < 64 && tp < L) {
            unsigned saddr = (unsigned)__cvta_generic_to_shared(&sRow[tp & (DEPTH - 1)][tid * 4]);
            const float* gaddr = lg + (size_t)tp * Vv + tid * 4;
            asm volatile("cp.async.cg.shared.global [%0], [%1], 16;\n"
                         :: "r"(saddr), "l"(gaddr));
        }
        asm volatile("cp.async.commit_group;\n");

        const float* row = sRow[t & (DEPTH - 1)];
        const float lse  = sLse[t];
        const float* ap  = &sAlpha[pb][2];
        float*       an  = &sAlpha[pb ^ 1][2];

        // state s0 = tid
        {
            float a  = ap[tid];
            float a1 = ap[tid - 1];                   // [-1] -> stored NEG pad
            float a2 = sk0 ? ap[tid - 2] : NEGV;
            float m  = fmaxf(a, fmaxf(a1, a2));
            float em = row[ext0] - lse;
            an[tid]  = v0 ? (m + em) : NEGV;
        }
        // state s1 = tid + 256
        {
            int s    = tid + 256;
            float a  = ap[s];
            float a1 = ap[s - 1];
            float a2 = sk1 ? ap[s - 2] : NEGV;
            float m  = fmaxf(a, fmaxf(a1, a2));
            float em = row[ext1] - lse;
            an[s]    = v1 ? (m + em) : NEGV;
        }
        // state 512 (last blank), only exists/valid when Ut == 256
        if (tid == 0) {
            float a  = ap[512];
            float a1 = ap[511];
            float em = row[0] - lse;
            an[512]  = v512 ? (fmaxf(a, a1) + em) : NEGV;
        }
        pb ^= 1;
    }
    __syncthreads();

    if (tid == 0) {
        const float* af = &sAlpha[pb][2];
        float vb = af[2 * Ut];       // final blank state
        float vl = af[2 * Ut - 1];   // final label state
        g_nll[b] = -fmaxf(vb, vl);   // masked nll sum for batch b (Viterbi score)
    }
}

// ---------------------------------------------------------------------------
// Kernel 3: deterministic fixed-order reduction to scalar loss
// ---------------------------------------------------------------------------
__global__ void finalize_kernel(const int* __restrict__ loglen, float* __restrict__ out) {
    float s = 0.0f, cnt = 0.0f;
    for (int b = 0; b < Bb; ++b) {
        s   += g_nll[b];
        cnt += (float)loglen[b];
    }
    out[0] = s / cnt;
}

// ---------------------------------------------------------------------------
extern "C" void kernel_launch(void* const* d_in, const int* in_sizes, int n_in,
                              void* d_out, int out_size) {
    const float* logits  = (const float*)d_in[0];
    const int*   targets = (const int*)d_in[1];
    const int*   loglen  = (const int*)d_in[2];
    const int*   tgtlen  = (const int*)d_in[3];

    lse_kernel<<<(Bb * Tt) / 8, 256>>>(logits);
    dp_kernel<<<Bb, 256>>>(logits, targets, loglen, tgtlen);
    finalize_kernel<<<1, 1>>>(loglen, (float*)d_out);
}

// round 2
// speedup vs baseline: 1.7422x; 1.7422x over previous
#include <cuda_runtime.h>
#include <math.h>

#define Bb 64
#define Tt 2048
#define Vv 256
#define Uu 256
#define NEGV (-1e30f)

// DP ring
#define DEPTH 32
#define PD 24
#define SLOTF 264        // 256 d-values + blank scalar + pad (16B aligned)

__device__ float g_d[(size_t)Bb * Tt * 256];   // d[b,t,i] = logits[b,t,tgt[i]] - logits[b,t,0]
__device__ float g_blank[Bb * Tt];             // logp[b,t,blank]
__device__ float g_nll[Bb];

__device__ __forceinline__ void cp16(unsigned sa, const float* g) {
    asm volatile("cp.async.cg.shared.global [%0], [%1], 16;\n" :: "r"(sa), "l"(g) : "memory");
}
__device__ __forceinline__ void cp4(unsigned sa, const float* g) {
    asm volatile("cp.async.ca.shared.global [%0], [%1], 4;\n" :: "r"(sa), "l"(g) : "memory");
}
__device__ __forceinline__ void cpcommit() {
    asm volatile("cp.async.commit_group;\n" ::: "memory");
}
template<int N> __device__ __forceinline__ void cpwait() {
    asm volatile("cp.async.wait_group %0;\n" :: "n"(N) : "memory");
}

// ---------------------------------------------------------------------------
// Kernel 1: fused lse + emission-delta gather.
//   d[b,t,i]     = logits[b,t,tgt[b,i]] - logits[b,t,0]   (lse cancels)
//   g_blank[b,t] = logits[b,t,0] - lse(logits[b,t,:])
// Skips rows t >= L[b]. grid = (T/64, B), block = 256 (8 warps x 8 rows each).
// ---------------------------------------------------------------------------
#define GB_ROWS 64
__global__ void __launch_bounds__(256) gather_kernel(const float* __restrict__ logits,
                                                     const int*  __restrict__ targets,
                                                     const int*  __restrict__ loglen) {
    __shared__ int   sTgt[Uu];
    __shared__ float sRow[8][2][Vv];

    const int b  = blockIdx.y;
    const int c  = blockIdx.x;
    const int L  = loglen[b];
    const int t0 = c * GB_ROWS;
    if (t0 >= L) return;

    const int tid = threadIdx.x, w = tid >> 5, lane = tid & 31;
    sTgt[tid] = targets[b * Uu + tid];
    __syncthreads();

    const int tbase = t0 + w * 8;
    if (tbase >= L) return;                      // uniform per warp
    int nrows = L - tbase; if (nrows > 8) nrows = 8;

    const float* lg   = logits + ((size_t)b * Tt + tbase) * Vv;
    float*       dOut = g_d    + ((size_t)b * Tt + tbase) * 256;

    // prefetch row 0
    {
        unsigned sa = (unsigned)__cvta_generic_to_shared(&sRow[w][0][lane * 8]);
        cp16(sa, lg + lane * 8);
        cp16(sa + 16, lg + lane * 8 + 4);
    }
    cpcommit();

    for (int k = 0; k < nrows; ++k) {
        if (k + 1 < nrows) {
            unsigned sa = (unsigned)__cvta_generic_to_shared(&sRow[w][(k + 1) & 1][lane * 8]);
            const float* g = lg + (size_t)(k + 1) * Vv + lane * 8;
            cp16(sa, g);
            cp16(sa + 16, g + 4);
        }
        cpcommit();
        cpwait<1>();            // row k landed
        __syncwarp();

        const float* r = sRow[w][k & 1];
        float4 v0 = *(const float4*)&r[lane * 4];
        float4 v1 = *(const float4*)&r[128 + lane * 4];
        float s = __expf(v0.x) + __expf(v0.y) + __expf(v0.z) + __expf(v0.w)
                + __expf(v1.x) + __expf(v1.y) + __expf(v1.z) + __expf(v1.w);
#pragma unroll
        for (int o = 16; o; o >>= 1) s += __shfl_xor_sync(0xffffffffu, s, o);
        float lse = __logf(s);
        float r0  = __shfl_sync(0xffffffffu, v0.x, 0);     // logits[b,t,0]

        int4 tg0 = *(const int4*)&sTgt[lane * 8];
        int4 tg1 = *(const int4*)&sTgt[lane * 8 + 4];
        float4 d0, d1;
        d0.x = r[tg0.x] - r0;  d0.y = r[tg0.y] - r0;
        d0.z = r[tg0.z] - r0;  d0.w = r[tg0.w] - r0;
        d1.x = r[tg1.x] - r0;  d1.y = r[tg1.y] - r0;
        d1.z = r[tg1.z] - r0;  d1.w = r[tg1.w] - r0;

        *(float4*)&dOut[(size_t)k * 256 + lane * 8]     = d0;
        *(float4*)&dOut[(size_t)k * 256 + lane * 8 + 4] = d1;
        if (lane == 0) g_blank[b * Tt + tbase + k] = r0 - lse;
        __syncwarp();
    }
}

// ---------------------------------------------------------------------------
// Kernel 2: barrier-free Viterbi DP, one warp per batch.
// Pair i: E_i = alpha[2i] (blank), O_i = alpha[2i+1] (label). Lane owns 8 pairs.
//   E_i' = max(E_i, O_{i-1})                       (blank emission normalized to 0)
//   O_i' = max(O_i, E_i, O_{i-1} + gate_i) + d_i   (gate_i in {0, NEG})
// Each lane reads only bytes it cp.async'd itself -> no intra-warp sync needed.
// ---------------------------------------------------------------------------
__global__ void __launch_bounds__(32) dp_kernel(const int* __restrict__ targets,
                                                const int* __restrict__ loglen,
                                                const int* __restrict__ tgtlen) {
    __shared__ float sD[DEPTH][SLOTF];
    __shared__ float sE[257];
    __shared__ float sO[256];

    const int b    = blockIdx.x;
    const int lane = threadIdx.x;
    const int L    = loglen[b];
    const int Ut   = tgtlen[b];
    const float* emB = g_d + (size_t)b * Tt * 256;
    const float* blB = g_blank + b * Tt;

    const int ibase = lane * 8;
    float gate[8];
    {
        int prev = (ibase == 0) ? -1 : targets[b * Uu + ibase - 1];
#pragma unroll
        for (int j = 0; j < 8; ++j) {
            int cur = targets[b * Uu + ibase + j];
            gate[j] = (ibase + j >= 1 && cur != prev) ? 0.0f : NEGV;
            prev = cur;
        }
    }

    float E[8], O[8];
#pragma unroll
    for (int j = 0; j < 8; ++j) { E[j] = NEGV; O[j] = NEGV; }
    float Eex = NEGV;                 // state 512 (E_256), owned by lane 31
    if (lane == 0) E[0] = 0.0f;       // alpha_hat_{-1} seed: generic step gives correct t=0
    float C = 0.0f;

    // prologue: prefetch rows 0..PD-1
    for (int p = 0; p < PD; ++p) {
        if (p < L) {
            unsigned sa = (unsigned)__cvta_generic_to_shared(&sD[p][ibase]);
            const float* g = emB + (size_t)p * 256 + ibase;
            cp16(sa, g);
            cp16(sa + 16, g + 4);
            if (lane == 0) cp4((unsigned)__cvta_generic_to_shared(&sD[p][256]), blB + p);
        }
        cpcommit();
    }

    for (int t = 0; t < L; ++t) {
        cpwait<PD - 1>();                       // row t's group complete (own lanes' bytes)
        const int slot = t & (DEPTH - 1);
        const float* sp = sD[slot];
        float4 d0 = *(const float4*)&sp[ibase];
        float4 d1 = *(const float4*)&sp[ibase + 4];
        if (lane == 0) C += sp[256];

        const int tp = t + PD;
        if (tp < L) {
            const int sl2 = tp & (DEPTH - 1);
            unsigned sa = (unsigned)__cvta_generic_to_shared(&sD[sl2][ibase]);
            const float* g = emB + (size_t)tp * 256 + ibase;
            cp16(sa, g);
            cp16(sa + 16, g + 4);
            if (lane == 0) cp4((unsigned)__cvta_generic_to_shared(&sD[sl2][256]), blB + tp);
        }
        cpcommit();

        float pO = __shfl_up_sync(0xffffffffu, O[7], 1);
        if (lane == 0) pO = NEGV;
        const float oldO7 = O[7];

        float dv[8] = {d0.x, d0.y, d0.z, d0.w, d1.x, d1.y, d1.z, d1.w};
#pragma unroll
        for (int j = 0; j < 8; ++j) {
            float e = E[j], o = O[j];
            E[j] = fmaxf(e, pO);
            float cnd = pO + gate[j];
            O[j] = fmaxf(fmaxf(o, e), cnd) + dv[j];
            pO = o;
        }
        Eex = fmaxf(Eex, oldO7);                // E_256' = max(E_256, O_255) + 0
    }

#pragma unroll
    for (int j = 0; j < 8; ++j) { sE[ibase + j] = E[j]; sO[ibase + j] = O[j]; }
    if (lane == 31) sE[256] = Eex;
    __syncwarp();
    if (lane == 0) {
        float vb = sE[Ut];          // alpha_hat[2*Ut]
        float vl = sO[Ut - 1];      // alpha_hat[2*Ut - 1]
        g_nll[b] = -(fmaxf(vb, vl) + C);
    }
}

// ---------------------------------------------------------------------------
// Kernel 3: reduce to scalar loss (deterministic tree)
// ---------------------------------------------------------------------------
__global__ void __launch_bounds__(32) finalize_kernel(const int* __restrict__ loglen,
                                                      float* __restrict__ out) {
    int lane = threadIdx.x;
    float s = 0.0f, c = 0.0f;
    for (int b = lane; b < Bb; b += 32) { s += g_nll[b]; c += (float)loglen[b]; }
#pragma unroll
    for (int o = 16; o; o >>= 1) {
        s += __shfl_xor_sync(0xffffffffu, s, o);
        c += __shfl_xor_sync(0xffffffffu, c, o);
    }
    if (lane == 0) out[0] = s / c;
}

// ---------------------------------------------------------------------------
extern "C" void kernel_launch(void* const* d_in, const int* in_sizes, int n_in,
                              void* d_out, int out_size) {
    const float* logits  = (const float*)d_in[0];
    const int*   targets = (const int*)d_in[1];
    const int*   loglen  = (const int*)d_in[2];
    const int*   tgtlen  = (const int*)d_in[3];

    gather_kernel<<<dim3(Tt / GB_ROWS, Bb), 256>>>(logits, targets, loglen);
    dp_kernel<<<Bb, 32>>>(targets, loglen, tgtlen);
    finalize_kernel<<<1, 32>>>(loglen, (float*)d_out);
}

// round 3
// speedup vs baseline: 2.9149x; 1.6732x over previous
#include <cuda_runtime.h>
#include <math.h>

#define Bb 64
#define Tt 2048
#define Vv 256
#define Uu 256
#define NEGV (-1e30f)

__device__ float g_d[(size_t)Bb * Tt * 256];   // d[b,t,i] = logits[b,t,tgt[i]] - logits[b,t,0]
__device__ float g_Cpart[Bb * 256];            // per-8-row blank-logp partial sums (zero-init, chunks >= L never written)
__device__ float g_nll[Bb];

__device__ __forceinline__ void cp16(unsigned sa, const float* g) {
    asm volatile("cp.async.cg.shared.global [%0], [%1], 16;\n" :: "r"(sa), "l"(g) : "memory");
}
__device__ __forceinline__ void cpcommit() {
    asm volatile("cp.async.commit_group;\n" ::: "memory");
}
template<int N> __device__ __forceinline__ void cpwait() {
    asm volatile("cp.async.wait_group %0;\n" :: "n"(N) : "memory");
}

// ---------------------------------------------------------------------------
// Kernel 1: fused lse + emission-delta gather + blank-logp partial sums.
//   d[b,t,i]          = logits[b,t,tgt[b,i]] - logits[b,t,0]
//   g_Cpart[b,chunk]  = sum over chunk's valid rows of (logits[b,t,0] - lse)
// grid = (T/64, B), block = 256 (8 warps x 8 rows each), 4-deep row ring.
// ---------------------------------------------------------------------------
#define GB_ROWS 64
__global__ void __launch_bounds__(256) gather_kernel(const float* __restrict__ logits,
                                                     const int*  __restrict__ targets,
                                                     const int*  __restrict__ loglen) {
    __shared__ int   sTgt[Uu];
    __shared__ float sRow[8][4][Vv];

    const int b  = blockIdx.y;
    const int c  = blockIdx.x;
    const int L  = loglen[b];
    const int t0 = c * GB_ROWS;
    if (t0 >= L) return;

    const int tid = threadIdx.x, w = tid >> 5, lane = tid & 31;
    sTgt[tid] = targets[b * Uu + tid];
    __syncthreads();

    const int tbase = t0 + w * 8;
    if (tbase >= L) return;                      // uniform per warp
    int nrows = L - tbase; if (nrows > 8) nrows = 8;

    const float* lg   = logits + ((size_t)b * Tt + tbase) * Vv;
    float*       dOut = g_d    + ((size_t)b * Tt + tbase) * 256;

    // prefetch rows 0..2
#pragma unroll
    for (int p = 0; p < 3; ++p) {
        if (p < nrows) {
            unsigned sa = (unsigned)__cvta_generic_to_shared(&sRow[w][p][lane * 8]);
            const float* g = lg + (size_t)p * Vv + lane * 8;
            cp16(sa, g);
            cp16(sa + 16, g + 4);
        }
        cpcommit();
    }

    float cb = 0.0f;
    for (int k = 0; k < nrows; ++k) {
        int pf = k + 3;
        if (pf < nrows) {
            unsigned sa = (unsigned)__cvta_generic_to_shared(&sRow[w][pf & 3][lane * 8]);
            const float* g = lg + (size_t)pf * Vv + lane * 8;
            cp16(sa, g);
            cp16(sa + 16, g + 4);
        }
        cpcommit();
        cpwait<3>();            // row k landed
        __syncwarp();

        const float* r = sRow[w][k & 3];
        float4 v0 = *(const float4*)&r[lane * 4];
        float4 v1 = *(const float4*)&r[128 + lane * 4];
        float s = __expf(v0.x) + __expf(v0.y) + __expf(v0.z) + __expf(v0.w)
                + __expf(v1.x) + __expf(v1.y) + __expf(v1.z) + __expf(v1.w);
#pragma unroll
        for (int o = 16; o; o >>= 1) s += __shfl_xor_sync(0xffffffffu, s, o);
        float lse = __logf(s);
        float r0  = __shfl_sync(0xffffffffu, v0.x, 0);     // logits[b,t,0]
        cb += r0 - lse;                                     // logp(blank) at this row

        int4 tg0 = *(const int4*)&sTgt[lane * 8];
        int4 tg1 = *(const int4*)&sTgt[lane * 8 + 4];
        float4 d0, d1;
        d0.x = r[tg0.x] - r0;  d0.y = r[tg0.y] - r0;
        d0.z = r[tg0.z] - r0;  d0.w = r[tg0.w] - r0;
        d1.x = r[tg1.x] - r0;  d1.y = r[tg1.y] - r0;
        d1.z = r[tg1.z] - r0;  d1.w = r[tg1.w] - r0;

        *(float4*)&dOut[(size_t)k * 256 + lane * 8]     = d0;
        *(float4*)&dOut[(size_t)k * 256 + lane * 8 + 4] = d1;
        __syncwarp();           // all lanes done with row k before its slot is reused
    }
    if (lane == 0) g_Cpart[b * 256 + (tbase >> 3)] = cb;
}

// ---------------------------------------------------------------------------
// Kernel 2: barrier-free Viterbi DP, one warp per batch.
// Pair i: E_i = alpha[2i] (blank), O_i = alpha[2i+1] (label). Lane owns 8 pairs.
//   E_i' = max(E_i, O_{i-1})
//   O_i' = max(O_i, E_i, O_{i-1} + gate_i) + d_i   (gate_i in {0, NEG})
// d streamed via cp.async ring (4 rows/group, 6 groups in flight), each lane
// reads only its own bytes -> no syncs. d register-double-buffered (buf[2][8]).
// ---------------------------------------------------------------------------
#define DPG 6
#define DROWS 32
__global__ void __launch_bounds__(32) dp_kernel(const int* __restrict__ targets,
                                                const int* __restrict__ loglen,
                                                const int* __restrict__ tgtlen) {
    __shared__ float sD[DROWS * 256];
    __shared__ float sE[257];
    __shared__ float sO[256];

    const int b    = blockIdx.x;
    const int lane = threadIdx.x;
    const int L    = loglen[b];
    const int Ut   = tgtlen[b];
    const float* emB = g_d + (size_t)b * Tt * 256;
    const int ibase = lane * 8;
    const unsigned sdBase = (unsigned)__cvta_generic_to_shared(sD);

    float gate[8];
    {
        int prev = (lane == 0) ? -1 : targets[b * Uu + ibase - 1];
#pragma unroll
        for (int j = 0; j < 8; ++j) {
            int cur = targets[b * Uu + ibase + j];
            gate[j] = (ibase + j >= 1 && cur != prev) ? 0.0f : NEGV;
            prev = cur;
        }
    }
    const float pOmask = (lane == 0) ? NEGV : 0.0f;

    float E[8], O[8];
#pragma unroll
    for (int j = 0; j < 8; ++j) { E[j] = NEGV; O[j] = NEGV; }
    float Eex = NEGV;
    if (lane == 0) E[0] = 0.0f;   // alpha_hat seed

#define ISSUE4(ROW0)                                                          \
    {                                                                         \
        _Pragma("unroll")                                                     \
        for (int r_ = 0; r_ < 4; ++r_) {                                      \
            int row_ = (ROW0) + r_;                                           \
            if (row_ < L) {                                                   \
                unsigned sa_ = sdBase + ((((unsigned)row_ & 31u) << 8) + ibase) * 4u; \
                const float* g_ = emB + (size_t)row_ * 256 + ibase;           \
                cp16(sa_, g_);                                                \
                cp16(sa_ + 16, g_ + 4);                                       \
            }                                                                 \
        }                                                                     \
        cpcommit();                                                           \
    }

#pragma unroll
    for (int g2 = 0; g2 < DPG; ++g2) ISSUE4(g2 * 4);
    cpwait<DPG - 2>();            // blocks 0,1 resident

    float buf[2][8];
    {   // preload row 0 into buf[0]
        const float* sp = sD + ibase;
        *(float4*)&buf[0][0] = *(const float4*)sp;
        *(float4*)&buf[0][4] = *(const float4*)(sp + 4);
    }

    const int nblk = L >> 2;
    const int rem  = L & 3;

#define SUBSTEP(KPAR, T)                                                      \
    {                                                                         \
        /* prefetch row T+1 into the other buffer */                          \
        const float* sp_ = sD + ((((T) + 1) & 31) << 8) + ibase;              \
        *(float4*)&buf[((KPAR) + 1) & 1][0] = *(const float4*)sp_;            \
        *(float4*)&buf[((KPAR) + 1) & 1][4] = *(const float4*)(sp_ + 4);      \
        float pO = __shfl_up_sync(0xffffffffu, O[7], 1) + pOmask;             \
        float oldO7 = O[7];                                                   \
        _Pragma("unroll")                                                     \
        for (int j = 0; j < 8; ++j) {                                         \
            float e = E[j], o = O[j], d = buf[(KPAR) & 1][j];                 \
            E[j] = fmaxf(e, pO);                                              \
            float cnd = pO + gate[j];                                         \
            O[j] = fmaxf(fmaxf(o, e), cnd) + d;                               \
            pO = o;                                                           \
        }                                                                     \
        Eex = fmaxf(Eex, oldO7);                                              \
    }

    for (int blk = 0; blk < nblk; ++blk) {
        ISSUE4((blk + DPG) * 4);
        cpwait<DPG - 2>();        // block blk+1 (and blk+2) resident
        const int t0 = blk * 4;
#pragma unroll
        for (int k = 0; k < 4; ++k) {
            SUBSTEP(k, t0 + k);
        }
    }

    // tail (<= 3 steps); all remaining groups drained
    cpwait<0>();
#pragma unroll
    for (int k = 0; k < 3; ++k) {
        if (k < rem) {
            SUBSTEP(k, nblk * 4 + k);
        }
    }

    // fold in blank-logp sum C_b (deterministic fixed pattern)
    float Cacc = 0.0f;
#pragma unroll
    for (int j = 0; j < 8; ++j) Cacc += g_Cpart[b * 256 + ibase + j];
#pragma unroll
    for (int o2 = 16; o2; o2 >>= 1) Cacc += __shfl_xor_sync(0xffffffffu, Cacc, o2);

#pragma unroll
    for (int j = 0; j < 8; ++j) { sE[ibase + j] = E[j]; sO[ibase + j] = O[j]; }
    if (lane == 31) sE[256] = Eex;
    __syncwarp();
    if (lane == 0) {
        float vb = sE[Ut];          // alpha_hat[2*Ut]
        float vl = sO[Ut - 1];      // alpha_hat[2*Ut - 1]
        g_nll[b] = -(fmaxf(vb, vl) + Cacc);
    }
#undef SUBSTEP
#undef ISSUE4
}

// ---------------------------------------------------------------------------
// Kernel 3: reduce to scalar loss (fixed-order, deterministic)
// ---------------------------------------------------------------------------
__global__ void __launch_bounds__(32) finalize_kernel(const int* __restrict__ loglen,
                                                      float* __restrict__ out) {
    int lane = threadIdx.x;
    float s = 0.0f, c = 0.0f;
    for (int bb = lane; bb < Bb; bb += 32) { s += g_nll[bb]; c += (float)loglen[bb]; }
#pragma unroll
    for (int o = 16; o; o >>= 1) {
        s += __shfl_xor_sync(0xffffffffu, s, o);
        c += __shfl_xor_sync(0xffffffffu, c, o);
    }
    if (lane == 0) out[0] = s / c;
}

// ---------------------------------------------------------------------------
extern "C" void kernel_launch(void* const* d_in, const int* in_sizes, int n_in,
                              void* d_out, int out_size) {
    const float* logits  = (const float*)d_in[0];
    const int*   targets = (const int*)d_in[1];
    const int*   loglen  = (const int*)d_in[2];
    const int*   tgtlen  = (const int*)d_in[3];

    gather_kernel<<<dim3(Tt / GB_ROWS, Bb), 256>>>(logits, targets, loglen);
    dp_kernel<<<Bb, 32>>>(targets, loglen, tgtlen);
    finalize_kernel<<<1, 32>>>(loglen, (float*)d_out);
}

// round 4
// speedup vs baseline: 3.0456x; 1.0448x over previous
#include <cuda_runtime.h>
#include <math.h>

#define Bb 64
#define Tt 2048
#define Vv 256
#define Uu 256
#define NEGV (-1e30f)

__device__ float g_d[(size_t)Bb * Tt * 256];   // d[b,t,i] = logits[b,t,tgt[i]] - logits[b,t,0]
__device__ float g_Cpart[Bb * 256];            // per-8-row blank-logp partial sums
__device__ float g_nll[Bb];

__device__ __forceinline__ void cp16(unsigned sa, const float* g) {
    asm volatile("cp.async.cg.shared.global [%0], [%1], 16;\n" :: "r"(sa), "l"(g) : "memory");
}
__device__ __forceinline__ void cpcommit() {
    asm volatile("cp.async.commit_group;\n" ::: "memory");
}
template<int N> __device__ __forceinline__ void cpwait() {
    asm volatile("cp.async.wait_group %0;\n" :: "n"(N) : "memory");
}

// ---------------------------------------------------------------------------
// Kernel 1: fused lse + emission-delta gather + blank-logp partial sums.
// (unchanged from R3: 37.8us, DRAM 50%)
// ---------------------------------------------------------------------------
#define GB_ROWS 64
__global__ void __launch_bounds__(256) gather_kernel(const float* __restrict__ logits,
                                                     const int*  __restrict__ targets,
                                                     const int*  __restrict__ loglen) {
    __shared__ int   sTgt[Uu];
    __shared__ float sRow[8][4][Vv];

    const int b  = blockIdx.y;
    const int c  = blockIdx.x;
    const int L  = loglen[b];
    const int t0 = c * GB_ROWS;
    if (t0 >= L) return;

    const int tid = threadIdx.x, w = tid >> 5, lane = tid & 31;
    sTgt[tid] = targets[b * Uu + tid];
    __syncthreads();

    const int tbase = t0 + w * 8;
    if (tbase >= L) return;
    int nrows = L - tbase; if (nrows > 8) nrows = 8;

    const float* lg   = logits + ((size_t)b * Tt + tbase) * Vv;
    float*       dOut = g_d    + ((size_t)b * Tt + tbase) * 256;

#pragma unroll
    for (int p = 0; p < 3; ++p) {
        if (p < nrows) {
            unsigned sa = (unsigned)__cvta_generic_to_shared(&sRow[w][p][lane * 8]);
            const float* g = lg + (size_t)p * Vv + lane * 8;
            cp16(sa, g);
            cp16(sa + 16, g + 4);
        }
        cpcommit();
    }

    float cb = 0.0f;
    for (int k = 0; k < nrows; ++k) {
        int pf = k + 3;
        if (pf < nrows) {
            unsigned sa = (unsigned)__cvta_generic_to_shared(&sRow[w][pf & 3][lane * 8]);
            const float* g = lg + (size_t)pf * Vv + lane * 8;
            cp16(sa, g);
            cp16(sa + 16, g + 4);
        }
        cpcommit();
        cpwait<3>();
        __syncwarp();

        const float* r = sRow[w][k & 3];
        float4 v0 = *(const float4*)&r[lane * 4];
        float4 v1 = *(const float4*)&r[128 + lane * 4];
        float s = __expf(v0.x) + __expf(v0.y) + __expf(v0.z) + __expf(v0.w)
                + __expf(v1.x) + __expf(v1.y) + __expf(v1.z) + __expf(v1.w);
#pragma unroll
        for (int o = 16; o; o >>= 1) s += __shfl_xor_sync(0xffffffffu, s, o);
        float lse = __logf(s);
        float r0  = __shfl_sync(0xffffffffu, v0.x, 0);
        cb += r0 - lse;

        int4 tg0 = *(const int4*)&sTgt[lane * 8];
        int4 tg1 = *(const int4*)&sTgt[lane * 8 + 4];
        float4 d0, d1;
        d0.x = r[tg0.x] - r0;  d0.y = r[tg0.y] - r0;
        d0.z = r[tg0.z] - r0;  d0.w = r[tg0.w] - r0;
        d1.x = r[tg1.x] - r0;  d1.y = r[tg1.y] - r0;
        d1.z = r[tg1.z] - r0;  d1.w = r[tg1.w] - r0;

        *(float4*)&dOut[(size_t)k * 256 + lane * 8]     = d0;
        *(float4*)&dOut[(size_t)k * 256 + lane * 8 + 4] = d1;
        __syncwarp();
    }
    if (lane == 0) g_Cpart[b * 256 + (tbase >> 3)] = cb;
}

// ---------------------------------------------------------------------------
// Kernel 2: barrier-free Viterbi DP, one warp per batch, early-shuffle.
// Pair i: E_i = alpha[2i] (blank), O_i = alpha[2i+1] (label). Lane owns 8 pairs.
//   E_i' = max(E_i, O_{i-1})
//   O_i' = max(O_i, E_i, O_{i-1} + gate_i) + d_i
// O[7]' is computed FIRST each step and its shfl_up issued immediately; the
// result is consumed only at the NEXT step, hiding the 26-cyc SHFL latency.
// ---------------------------------------------------------------------------
#define DPG 6
#define DROWS 32
__global__ void __launch_bounds__(32) dp_kernel(const int* __restrict__ targets,
                                                const int* __restrict__ loglen,
                                                const int* __restrict__ tgtlen) {
    __shared__ float sD[DROWS * 256];
    __shared__ float sE[257];
    __shared__ float sO[256];

    const int b    = blockIdx.x;
    const int lane = threadIdx.x;
    const int L    = loglen[b];
    const int Ut   = tgtlen[b];
    const float* emB = g_d + (size_t)b * Tt * 256;
    const int ibase = lane * 8;
    const unsigned sdBase = (unsigned)__cvta_generic_to_shared(sD);

    float gate[8];
    {
        int prev = (lane == 0) ? -1 : targets[b * Uu + ibase - 1];
#pragma unroll
        for (int j = 0; j < 8; ++j) {
            int cur = targets[b * Uu + ibase + j];
            gate[j] = (ibase + j >= 1 && cur != prev) ? 0.0f : NEGV;
            prev = cur;
        }
    }
    const float pOmask = (lane == 0) ? NEGV : 0.0f;

    float E[8], O[8];
#pragma unroll
    for (int j = 0; j < 8; ++j) { E[j] = NEGV; O[j] = NEGV; }
    float Eex = NEGV;
    if (lane == 0) E[0] = 0.0f;   // alpha_hat seed
    float pO_cur = NEGV;          // masked pO for j=0 of the upcoming step

#define ISSUE4U(ROW0)                                                         \
    {                                                                         \
        _Pragma("unroll")                                                     \
        for (int r_ = 0; r_ < 4; ++r_) {                                      \
            int row_ = (ROW0) + r_;                                           \
            unsigned sa_ = sdBase + ((((unsigned)row_ & 31u) << 8) + ibase) * 4u; \
            const float* g_ = emB + (size_t)row_ * 256 + ibase;               \
            cp16(sa_, g_);                                                    \
            cp16(sa_ + 16, g_ + 4);                                           \
        }                                                                     \
        cpcommit();                                                           \
    }
#define ISSUE4G(ROW0)                                                         \
    {                                                                         \
        _Pragma("unroll")                                                     \
        for (int r_ = 0; r_ < 4; ++r_) {                                      \
            int row_ = (ROW0) + r_;                                           \
            if (row_ < L) {                                                   \
                unsigned sa_ = sdBase + ((((unsigned)row_ & 31u) << 8) + ibase) * 4u; \
                const float* g_ = emB + (size_t)row_ * 256 + ibase;           \
                cp16(sa_, g_);                                                \
                cp16(sa_ + 16, g_ + 4);                                       \
            }                                                                 \
        }                                                                     \
        cpcommit();                                                           \
    }

#pragma unroll
    for (int g2 = 0; g2 < DPG; ++g2) ISSUE4U(g2 * 4);   // L >= 1024 >> 24
    cpwait<DPG - 2>();

    float buf[2][8];
    {
        const float* sp = sD + ibase;
        *(float4*)&buf[0][0] = *(const float4*)sp;
        *(float4*)&buf[0][4] = *(const float4*)(sp + 4);
    }

    const int nblk = L >> 2;
    const int rem  = L & 3;

#define SUBSTEP(KPAR, T)                                                      \
    {                                                                         \
        /* prefetch row T+1 into the other buffer */                          \
        const float* sp_ = sD + ((((T) + 1) & 31) << 8) + ibase;              \
        *(float4*)&buf[((KPAR) + 1) & 1][0] = *(const float4*)sp_;            \
        *(float4*)&buf[((KPAR) + 1) & 1][4] = *(const float4*)(sp_ + 4);      \
        const float* dv = buf[(KPAR) & 1];                                    \
        /* j=7 first: its input O[6] is ready at step entry */                \
        float e7 = E[7], o7 = O[7];                                           \
        float O7n = fmaxf(fmaxf(o7, e7), O[6] + gate[7]) + dv[7];             \
        float E7n = fmaxf(e7, O[6]);                                          \
        float nextPO = __shfl_up_sync(0xffffffffu, O7n, 1);  /* early issue */\
        float pO = pO_cur;                                                    \
        _Pragma("unroll")                                                     \
        for (int j = 0; j < 7; ++j) {                                         \
            float e = E[j], o = O[j];                                         \
            E[j] = fmaxf(e, pO);                                              \
            float cnd = pO + gate[j];                                         \
            O[j] = fmaxf(fmaxf(o, e), cnd) + dv[j];                           \
            pO = o;                                                           \
        }                                                                     \
        Eex = fmaxf(Eex, o7);                                                 \
        E[7] = E7n; O[7] = O7n;                                               \
        pO_cur = nextPO + pOmask;   /* consumed next step */                  \
    }

    const int nfast = nblk - DPG;          // groups whose prefetch needs no guard
    int blk = 0;
    for (; blk < nfast; ++blk) {
        ISSUE4U((blk + DPG) * 4);
        cpwait<DPG - 2>();
        const int t0 = blk * 4;
#pragma unroll
        for (int k = 0; k < 4; ++k) { SUBSTEP(k, t0 + k); }
    }
    for (; blk < nblk; ++blk) {
        ISSUE4G((blk + DPG) * 4);
        cpwait<DPG - 2>();
        const int t0 = blk * 4;
#pragma unroll
        for (int k = 0; k < 4; ++k) { SUBSTEP(k, t0 + k); }
    }

    // tail (<= 3 steps)
    cpwait<0>();
#pragma unroll
    for (int k = 0; k < 3; ++k) {
        if (k < rem) { SUBSTEP(k, nblk * 4 + k); }
    }

    // fold in blank-logp sum C_b (deterministic fixed pattern)
    float Cacc = 0.0f;
#pragma unroll
    for (int j = 0; j < 8; ++j) Cacc += g_Cpart[b * 256 + ibase + j];
#pragma unroll
    for (int o2 = 16; o2; o2 >>= 1) Cacc += __shfl_xor_sync(0xffffffffu, Cacc, o2);

#pragma unroll
    for (int j = 0; j < 8; ++j) { sE[ibase + j] = E[j]; sO[ibase + j] = O[j]; }
    if (lane == 31) sE[256] = Eex;
    __syncwarp();
    if (lane == 0) {
        float vb = sE[Ut];
        float vl = sO[Ut - 1];
        g_nll[b] = -(fmaxf(vb, vl) + Cacc);
    }
#undef SUBSTEP
#undef ISSUE4U
#undef ISSUE4G
}

// ---------------------------------------------------------------------------
// Kernel 3: reduce to scalar loss (fixed-order, deterministic)
// ---------------------------------------------------------------------------
__global__ void __launch_bounds__(32) finalize_kernel(const int* __restrict__ loglen,
                                                      float* __restrict__ out) {
    int lane = threadIdx.x;
    float s = 0.0f, c = 0.0f;
    for (int bb = lane; bb < Bb; bb += 32) { s += g_nll[bb]; c += (float)loglen[bb]; }
#pragma unroll
    for (int o = 16; o; o >>= 1) {
        s += __shfl_xor_sync(0xffffffffu, s, o);
        c += __shfl_xor_sync(0xffffffffu, c, o);
    }
    if (lane == 0) out[0] = s / c;
}

// ---------------------------------------------------------------------------
extern "C" void kernel_launch(void* const* d_in, const int* in_sizes, int n_in,
                              void* d_out, int out_size) {
    const float* logits  = (const float*)d_in[0];
    const int*   targets = (const int*)d_in[1];
    const int*   loglen  = (const int*)d_in[2];
    const int*   tgtlen  = (const int*)d_in[3];

    gather_kernel<<<dim3(Tt / GB_ROWS, Bb), 256>>>(logits, targets, loglen);
    dp_kernel<<<Bb, 32>>>(targets, loglen, tgtlen);
    finalize_kernel<<<1, 32>>>(loglen, (float*)d_out);
}